// round 6
// baseline (speedup 1.0000x reference)
#include <cuda_runtime.h>
#include <mma.h>
using namespace nvcuda;

// Problem constants
#define BATCH   4
#define SEQLEN  65536
#define RC      32
#define OC      256
#define NBLOCKS 2
#define NLAYERS 10

#define TL      128           // positions per CTA in k_layer_tc
#define FGLD    132           // staging row stride
#define WALD1   72            // GEMM1 A stride: tap0(0-31) tap1(32-63) bias(64) zero(65-71)
#define WALD2   40            // GEMM2 A stride: w(0-31) bias(32) zero(33-39)
// fixed smem (floats): lo[40][FGLD] + fg[64][FGLD] + wA1[64][WALD1] + wA2[64][WALD2]
#define SM_FIXED (40 * FGLD + 64 * FGLD + 64 * WALD1 + 64 * WALD2)

#define HLDH    132           // head hidden row stride

// -------- scratch (device globals; no allocation allowed) --------
__device__ float g_resid[2][BATCH * RC * SEQLEN];
__device__ float g_skip[BATCH * RC * SEQLEN];
__device__ float g_w1e[OC * 40];      // [256][40]: w1 | b1 | 0
__device__ float g_w2e[OC * 264];     // [256][264]: w2 | b2 | 0

// ----------------------------------------------------------------
// Kernel 1: start conv (1 -> 32, 1x1).
// ----------------------------------------------------------------
__global__ void k_start(const float* __restrict__ x,
                        const float* __restrict__ w,
                        const float* __restrict__ bias)
{
    size_t idx = (size_t)blockIdx.x * blockDim.x + threadIdx.x;
    if (idx >= (size_t)BATCH * RC * SEQLEN) return;
    int l = (int)(idx % SEQLEN);
    int c = (int)((idx / SEQLEN) % RC);
    int b = (int)(idx / ((size_t)RC * SEQLEN));
    g_resid[0][idx] = w[c] * x[(size_t)b * SEQLEN + l] + bias[c];
}

// ----------------------------------------------------------------
// Prep: bias-extended head weights.
// ----------------------------------------------------------------
__global__ void k_prepw(const float* __restrict__ w1, const float* __restrict__ b1,
                        const float* __restrict__ w2, const float* __restrict__ b2)
{
    int idx = blockIdx.x * blockDim.x + threadIdx.x;
    const int N2 = OC * 264;
    if (idx < N2) {
        int m = idx / 264, c = idx % 264;
        g_w2e[idx] = (c < 256) ? w2[(size_t)m * 256 + c] : (c == 256 ? b2[m] : 0.f);
    } else if (idx < N2 + OC * 40) {
        int j = idx - N2;
        int m = j / 40, c = j % 40;
        g_w1e[j] = (c < 32) ? w1[(size_t)m * 32 + c] : (c == 32 ? b1[m] : 0.f);
    }
}

// ----------------------------------------------------------------
// Kernel 2: gated dilated layer, TF32 wmma, register-fused gating.
// GEMM1 K-ext: taps (2x32) + bias chunk (halo row32=1, rows33-39=0).
// lo = accF * accG on fragments; GEMM2 K-ext: 32 + bias chunk.
// ----------------------------------------------------------------
__global__ __launch_bounds__(256, 2)
void k_layer_tc(int ping,
                const float* __restrict__ fw, const float* __restrict__ fb,
                const float* __restrict__ gw, const float* __restrict__ gb,
                const float* __restrict__ rw, const float* __restrict__ rb,
                const float* __restrict__ sw, const float* __restrict__ sb,
                int offA, int offB, int PAD, int HS, int skipInit)
{
    extern __shared__ float smem[];
    float* halo = smem;                     // [40][HS]; col PAD+n <-> l0+n
    float* lo   = smem + 40 * HS;           // [40][FGLD]
    float* fg   = lo + 40 * FGLD;           // [64][FGLD]
    float* wA1  = fg + 64 * FGLD;           // [64][WALD1]
    float* wA2  = wA1 + 64 * WALD1;         // [64][WALD2]

    int tid = threadIdx.x;
    int b = blockIdx.y;
    int l0 = blockIdx.x * TL;

    const float* __restrict__ rin = &g_resid[ping][(size_t)b * RC * SEQLEN];
    float* __restrict__ rout = &g_resid[ping ^ 1][(size_t)b * RC * SEQLEN];
    float* __restrict__ sk = &g_skip[(size_t)b * RC * SEQLEN];

    // --- GEMM1 A: rows 0-31 filt, 32-63 gate; cols tap0|tap1|bias|0
    const float2* fw2 = (const float2*)fw;
    const float2* gw2 = (const float2*)gw;
    for (int i = tid; i < 64 * WALD1; i += 256) {
        int row = i / WALD1, col = i - row * WALD1;
        int c = row & 31;
        float v = 0.f;
        if (col < 32) {
            float2 t = (row < 32) ? fw2[c * 32 + col] : gw2[c * 32 + col];
            v = t.x;
        } else if (col < 64) {
            float2 t = (row < 32) ? fw2[c * 32 + (col - 32)] : gw2[c * 32 + (col - 32)];
            v = t.y;
        } else if (col == 64) {
            v = (row < 32) ? fb[c] : gb[c];
        }
        wA1[i] = v;
    }
    // --- GEMM2 A: rows 0-31 res, 32-63 skip; cols w|bias|0
    for (int i = tid; i < 64 * WALD2; i += 256) {
        int row = i / WALD2, col = i - row * WALD2;
        int c = row & 31;
        float v = 0.f;
        if (col < 32)      v = (row < 32) ? rw[c * 32 + col] : sw[c * 32 + col];
        else if (col == 32) v = (row < 32) ? rb[c] : sb[c];
        wA2[i] = v;
    }
    // --- lo rows 32-39: ones row + zeros (bias chunk for GEMM2)
    for (int i = tid; i < 8 * TL; i += 256) {
        int row = 32 + (i >> 7), col = i & 127;
        lo[row * FGLD + col] = (row == 32) ? 1.f : 0.f;
    }
    // --- halo rows 32-39: ones row + zeros (bias chunk for GEMM1)
    for (int i = tid; i < 8 * HS; i += 256) {
        int row = 32 + i / HS, col = i - (row - 32) * HS;
        halo[row * HS + col] = (row == 32) ? 1.f : 0.f;
    }
    // --- residual halo (zero-padded OOB); PAD, l0 multiples of 4
    {
        int c0 = (PAD + offA) & ~3;
        int c1 = (PAD + TL + offB + 4) & ~3;
        int w4 = (c1 - c0) >> 2;
        for (int i = tid; i < 32 * w4; i += 256) {
            int row = i / w4;
            int col = c0 + ((i - row * w4) << 2);
            int l = l0 - PAD + col;
            float4 v = make_float4(0.f, 0.f, 0.f, 0.f);
            if (l >= 0 && l < SEQLEN)
                v = *(const float4*)&rin[(size_t)row * SEQLEN + l];
            *(float4*)&halo[row * HS + col] = v;
        }
    }
    __syncthreads();

    int warp = tid >> 5;
    int lane = tid & 31;
    int n0 = warp * 16;
    int lcol = n0 + (lane & 15);
    int cbase = (lane >> 4) * 16;

    // ---------------- GEMM1: [f;g] = Wfg @ [shifted resid; 1] ----------------
    wmma::fragment<wmma::accumulator, 16, 16, 8, float> acc[4];
#pragma unroll
    for (int mi = 0; mi < 4; mi++) wmma::fill_fragment(acc[mi], 0.f);

#pragma unroll
    for (int kf = 0; kf < 9; kf++) {
        int brow, bcol;
        if (kf < 4)      { brow = kf * 8;       bcol = PAD + offA + n0; }
        else if (kf < 8) { brow = (kf - 4) * 8; bcol = PAD + offB + n0; }
        else             { brow = 32;           bcol = PAD + n0; }
        wmma::fragment<wmma::matrix_b, 16, 16, 8, wmma::precision::tf32, wmma::row_major> bf;
        wmma::load_matrix_sync(bf, &halo[brow * HS + bcol], HS);
#pragma unroll
        for (int t = 0; t < bf.num_elements; t++)
            bf.x[t] = wmma::__float_to_tf32(bf.x[t]);
#pragma unroll
        for (int mi = 0; mi < 4; mi++) {
            wmma::fragment<wmma::matrix_a, 16, 16, 8, wmma::precision::tf32, wmma::row_major> a;
            wmma::load_matrix_sync(a, &wA1[(mi * 16) * WALD1 + kf * 8], WALD1);
#pragma unroll
            for (int t = 0; t < a.num_elements; t++)
                a.x[t] = wmma::__float_to_tf32(a.x[t]);
            wmma::mma_sync(acc[mi], a, bf, acc[mi]);
        }
    }

    // ---------------- lo = f * g on fragments (identical layouts) ----------------
#pragma unroll
    for (int mi = 0; mi < 2; mi++) {
#pragma unroll
        for (int t = 0; t < acc[mi].num_elements; t++)
            acc[mi].x[t] *= acc[mi + 2].x[t];
        wmma::store_matrix_sync(&lo[(mi * 16) * FGLD + n0], acc[mi], FGLD, wmma::mem_row_major);
    }
    __syncwarp();

    // ---------------- GEMM2: [res;skip] = Wrs @ [lo; 1] ----------------
#pragma unroll
    for (int mi = 0; mi < 4; mi++) wmma::fill_fragment(acc[mi], 0.f);
#pragma unroll
    for (int kf = 0; kf < 5; kf++) {
        wmma::fragment<wmma::matrix_b, 16, 16, 8, wmma::precision::tf32, wmma::row_major> bf;
        wmma::load_matrix_sync(bf, &lo[(kf * 8) * FGLD + n0], FGLD);
#pragma unroll
        for (int t = 0; t < bf.num_elements; t++)
            bf.x[t] = wmma::__float_to_tf32(bf.x[t]);
#pragma unroll
        for (int mi = 0; mi < 4; mi++) {
            wmma::fragment<wmma::matrix_a, 16, 16, 8, wmma::precision::tf32, wmma::row_major> a;
            wmma::load_matrix_sync(a, &wA2[(mi * 16) * WALD2 + kf * 8], WALD2);
#pragma unroll
            for (int t = 0; t < a.num_elements; t++)
                a.x[t] = wmma::__float_to_tf32(a.x[t]);
            wmma::mma_sync(acc[mi], a, bf, acc[mi]);
        }
    }
#pragma unroll
    for (int mi = 0; mi < 4; mi++)
        wmma::store_matrix_sync(&fg[(mi * 16) * FGLD + n0], acc[mi], FGLD, wmma::mem_row_major);
    __syncwarp();

    // ---------------- residual + skip epilogue (biases already folded) ----------------
#pragma unroll
    for (int cc = 0; cc < 16; cc++) {
        int c = cbase + cc;
        size_t gidx = (size_t)c * SEQLEN + l0 + lcol;
        float rv = halo[c * HS + PAD + lcol] + fg[c * FGLD + lcol];
        float sv = fg[(32 + c) * FGLD + lcol];
        if (!skipInit) sv += sk[gidx];
        rout[gidx] = rv;
        sk[gidx] = sv;
    }
}

// ----------------------------------------------------------------
// Kernel 3: fused head.
//   hid = relu(W1e @ [relu(skip);1])   (in smem, 264 rows: 256 + ones + zeros)
//   out = W2e @ [hid;1]                (straight to gmem)
// CTA = 128 positions, all 256 outputs; 8 warps, warp = 32 out rows.
// W1e/W2e A tiles loaded directly from gmem (L2-resident).
// ----------------------------------------------------------------
__global__ __launch_bounds__(256, 1)
void k_head(float* __restrict__ out)
{
    extern __shared__ float smem[];
    float* hid = smem;                  // [264][HLDH]
    float* bsk = smem + 264 * HLDH;     // [40][HLDH]

    int tid = threadIdx.x;
    int b = blockIdx.y;
    int l0 = blockIdx.x * 128;

    // B tile: relu(skip) rows 0-31, row 32 = 1, rows 33-39 = 0
    for (int i = tid; i < 32 * 32; i += 256) {
        int row = i >> 5, n4 = (i & 31) << 2;
        float4 v = *(const float4*)&g_skip[((size_t)b * RC + row) * SEQLEN + l0 + n4];
        v.x = v.x > 0.f ? v.x : 0.f;
        v.y = v.y > 0.f ? v.y : 0.f;
        v.z = v.z > 0.f ? v.z : 0.f;
        v.w = v.w > 0.f ? v.w : 0.f;
        *(float4*)&bsk[row * HLDH + n4] = v;
    }
    for (int i = tid; i < 8 * 128; i += 256) {
        int row = 32 + (i >> 7), col = i & 127;
        bsk[row * HLDH + col] = (row == 32) ? 1.f : 0.f;
    }
    // hid bias rows: row 256 = 1, rows 257-263 = 0
    for (int i = tid; i < 8 * 128; i += 256) {
        int row = 256 + (i >> 7), col = i & 127;
        hid[row * HLDH + col] = (row == 256) ? 1.f : 0.f;
    }
    __syncthreads();

    int warp = tid >> 5;
    wmma::fragment<wmma::accumulator, 16, 16, 8, float> acc[2][8];

    // ---------------- GEMM1: hid rows warp*32..+31 ----------------
#pragma unroll
    for (int mi = 0; mi < 2; mi++)
#pragma unroll
        for (int ni = 0; ni < 8; ni++) wmma::fill_fragment(acc[mi][ni], 0.f);

#pragma unroll
    for (int kf = 0; kf < 5; kf++) {
        wmma::fragment<wmma::matrix_b, 16, 16, 8, wmma::precision::tf32, wmma::row_major> bf[8];
#pragma unroll
        for (int ni = 0; ni < 8; ni++) {
            wmma::load_matrix_sync(bf[ni], &bsk[(kf * 8) * HLDH + ni * 16], HLDH);
#pragma unroll
            for (int t = 0; t < bf[ni].num_elements; t++)
                bf[ni].x[t] = wmma::__float_to_tf32(bf[ni].x[t]);
        }
#pragma unroll
        for (int mi = 0; mi < 2; mi++) {
            wmma::fragment<wmma::matrix_a, 16, 16, 8, wmma::precision::tf32, wmma::row_major> a;
            wmma::load_matrix_sync(a, &g_w1e[(warp * 32 + mi * 16) * 40 + kf * 8], 40);
#pragma unroll
            for (int t = 0; t < a.num_elements; t++)
                a.x[t] = wmma::__float_to_tf32(a.x[t]);
#pragma unroll
            for (int ni = 0; ni < 8; ni++)
                wmma::mma_sync(acc[mi][ni], a, bf[ni], acc[mi][ni]);
        }
    }
    // relu on fragments, store hid
#pragma unroll
    for (int mi = 0; mi < 2; mi++)
#pragma unroll
        for (int ni = 0; ni < 8; ni++) {
#pragma unroll
            for (int t = 0; t < acc[mi][ni].num_elements; t++)
                acc[mi][ni].x[t] = acc[mi][ni].x[t] > 0.f ? acc[mi][ni].x[t] : 0.f;
            wmma::store_matrix_sync(&hid[(warp * 32 + mi * 16) * HLDH + ni * 16],
                                    acc[mi][ni], HLDH, wmma::mem_row_major);
        }
    __syncthreads();

    // ---------------- GEMM2: out rows warp*32..+31, K = 264 ----------------
#pragma unroll
    for (int mi = 0; mi < 2; mi++)
#pragma unroll
        for (int ni = 0; ni < 8; ni++) wmma::fill_fragment(acc[mi][ni], 0.f);

    for (int kf = 0; kf < 33; kf++) {
        wmma::fragment<wmma::matrix_b, 16, 16, 8, wmma::precision::tf32, wmma::row_major> bf[8];
#pragma unroll
        for (int ni = 0; ni < 8; ni++) {
            wmma::load_matrix_sync(bf[ni], &hid[(kf * 8) * HLDH + ni * 16], HLDH);
#pragma unroll
            for (int t = 0; t < bf[ni].num_elements; t++)
                bf[ni].x[t] = wmma::__float_to_tf32(bf[ni].x[t]);
        }
#pragma unroll
        for (int mi = 0; mi < 2; mi++) {
            wmma::fragment<wmma::matrix_a, 16, 16, 8, wmma::precision::tf32, wmma::row_major> a;
            wmma::load_matrix_sync(a, &g_w2e[(warp * 32 + mi * 16) * 264 + kf * 8], 264);
#pragma unroll
            for (int t = 0; t < a.num_elements; t++)
                a.x[t] = wmma::__float_to_tf32(a.x[t]);
#pragma unroll
            for (int ni = 0; ni < 8; ni++)
                wmma::mma_sync(acc[mi][ni], a, bf[ni], acc[mi][ni]);
        }
    }
#pragma unroll
    for (int mi = 0; mi < 2; mi++)
#pragma unroll
        for (int ni = 0; ni < 8; ni++) {
            float* dst = &out[((size_t)b * OC + warp * 32 + mi * 16) * SEQLEN
                              + l0 + ni * 16];
            wmma::store_matrix_sync(dst, acc[mi][ni], SEQLEN, wmma::mem_row_major);
        }
}

// ----------------------------------------------------------------
extern "C" void kernel_launch(void* const* d_in, const int* in_sizes, int n_in,
                              void* d_out, int out_size)
{
    const float* x       = (const float*)d_in[0];
    const float* w_start = (const float*)d_in[1];
    const float* b_start = (const float*)d_in[2];
    const float* filt_w  = (const float*)d_in[3];
    const float* filt_b  = (const float*)d_in[4];
    const float* gate_w  = (const float*)d_in[5];
    const float* gate_b  = (const float*)d_in[6];
    const float* res_w   = (const float*)d_in[7];
    const float* res_b   = (const float*)d_in[8];
    const float* skip_w  = (const float*)d_in[9];
    const float* skip_b  = (const float*)d_in[10];
    const float* w_end1  = (const float*)d_in[11];
    const float* b_end1  = (const float*)d_in[12];
    const float* w_end2  = (const float*)d_in[13];
    const float* b_end2  = (const float*)d_in[14];
    float* out = (float*)d_out;

    static int smem_set = 0;
    if (!smem_set) {
        int hsMax = (TL + 2 * 256 + 11) & ~3;
        cudaFuncSetAttribute(k_layer_tc, cudaFuncAttributeMaxDynamicSharedMemorySize,
                             (SM_FIXED + 40 * hsMax) * (int)sizeof(float));
        cudaFuncSetAttribute(k_head, cudaFuncAttributeMaxDynamicSharedMemorySize,
                             (264 * HLDH + 40 * HLDH) * (int)sizeof(float));
        smem_set = 1;
    }

    {
        size_t n = (size_t)BATCH * RC * SEQLEN;
        k_start<<<(unsigned)((n + 255) / 256), 256>>>(x, w_start, b_start);
    }
    {
        int n = OC * 264 + OC * 40;
        k_prepw<<<(n + 255) / 256, 256>>>(w_end1, b_end1, w_end2, b_end2);
    }

    int ping = 0;
    dim3 gl(SEQLEN / TL, BATCH);
    for (int blk = 0; blk < NBLOCKS; blk++) {
        for (int i = 0; i < NLAYERS; i++) {
            int li = blk * NLAYERS + i;
            int offA, offB;
            if (i == 0) { offA = -1; offB = 0; }
            else { int h = 1 << (i - 1); offA = -h; offB = h; }
            int CO = -offA > offB ? -offA : offB;
            int PAD = (CO + 3) & ~3;
            int HS = (TL + 2 * PAD + 11) & ~3;
            int smemBytes = (SM_FIXED + 40 * HS) * (int)sizeof(float);
            k_layer_tc<<<gl, 256, smemBytes>>>(ping,
                filt_w + (size_t)li * RC * RC * 2, filt_b + (size_t)li * RC,
                gate_w + (size_t)li * RC * RC * 2, gate_b + (size_t)li * RC,
                res_w  + (size_t)li * RC * RC,     res_b  + (size_t)li * RC,
                skip_w + (size_t)li * RC * RC,     skip_b + (size_t)li * RC,
                offA, offB, PAD, HS, (li == 0) ? 1 : 0);
            ping ^= 1;
        }
    }

    dim3 gh(SEQLEN / 128, BATCH);
    k_head<<<gh, 256, (264 * HLDH + 40 * HLDH) * sizeof(float)>>>(out);
}

// round 7
// speedup vs baseline: 1.3948x; 1.3948x over previous
#include <cuda_runtime.h>
#include <mma.h>
using namespace nvcuda;

// Problem constants
#define BATCH   4
#define SEQLEN  65536
#define RC      32
#define OC      256
#define NBLOCKS 2
#define NLAYERS 10

#define TL      128           // positions per CTA in k_layer_tc
#define FGLD    132           // f/g + output staging row stride
#define WALD    40            // weight A row stride
// fixed smem part (floats): fg[64][FGLD] + lo[32][FGLD] + wA[3][64][WALD] + bias[128]
#define SM_FIXED (64 * FGLD + 32 * FGLD + 3 * 64 * WALD + 128)

#define HLDH    132           // head row stride

// -------- scratch (device globals; no allocation allowed) --------
__device__ float g_resid[2][BATCH * RC * SEQLEN];
__device__ float g_skip[BATCH * RC * SEQLEN];
__device__ float g_w1e[OC * 40];      // [256][40]: tf32(w1) | tf32(b1) | 0
__device__ float g_w2e[OC * 264];     // [256][264]: tf32(w2) | tf32(b2) | 0

// ----------------------------------------------------------------
// Kernel 1: start conv (1 -> 32, 1x1).
// ----------------------------------------------------------------
__global__ void k_start(const float* __restrict__ x,
                        const float* __restrict__ w,
                        const float* __restrict__ bias)
{
    size_t idx = (size_t)blockIdx.x * blockDim.x + threadIdx.x;
    if (idx >= (size_t)BATCH * RC * SEQLEN) return;
    int l = (int)(idx % SEQLEN);
    int c = (int)((idx / SEQLEN) % RC);
    int b = (int)(idx / ((size_t)RC * SEQLEN));
    g_resid[0][idx] = w[c] * x[(size_t)b * SEQLEN + l] + bias[c];
}

// ----------------------------------------------------------------
// Prep: bias-extended head weights, pre-rounded to tf32.
// ----------------------------------------------------------------
__global__ void k_prepw(const float* __restrict__ w1, const float* __restrict__ b1,
                        const float* __restrict__ w2, const float* __restrict__ b2)
{
    int idx = blockIdx.x * blockDim.x + threadIdx.x;
    const int N2 = OC * 264;
    if (idx < N2) {
        int m = idx / 264, c = idx % 264;
        float v = (c < 256) ? w2[(size_t)m * 256 + c] : (c == 256 ? b2[m] : 0.f);
        g_w2e[idx] = wmma::__float_to_tf32(v);
    } else if (idx < N2 + OC * 40) {
        int j = idx - N2;
        int m = j / 40, c = j % 40;
        float v = (c < 32) ? w1[(size_t)m * 32 + c] : (c == 32 ? b1[m] : 0.f);
        g_w1e[j] = wmma::__float_to_tf32(v);
    }
}

// ----------------------------------------------------------------
// Kernel 2: gated dilated layer (R5 structure), TF32 wmma.
// Weights + lo stored pre-rounded to tf32 -> no conversion loops on
// A operands or GEMM2's B. Halo stays fp32 (residual carry path);
// only GEMM1's B fragments are converted at load.
// ----------------------------------------------------------------
__global__ __launch_bounds__(256, 2)
void k_layer_tc(int ping,
                const float* __restrict__ fw, const float* __restrict__ fb,
                const float* __restrict__ gw, const float* __restrict__ gb,
                const float* __restrict__ rw, const float* __restrict__ rb,
                const float* __restrict__ sw, const float* __restrict__ sb,
                int offA, int offB, int PAD, int HS, int skipInit)
{
    extern __shared__ float smem[];
    float* halo = smem;                 // [32][HS], col PAD+n <-> global l0+n
    float* fg   = smem + 32 * HS;       // [64][FGLD]
    float* lo   = fg + 64 * FGLD;       // [32][FGLD]
    float* wA   = lo + 32 * FGLD;       // [3][64][WALD], tf32-rounded
    float* bias = wA + 3 * 64 * WALD;   // [128]

    int tid = threadIdx.x;
    int b = blockIdx.y;
    int l0 = blockIdx.x * TL;

    const float* __restrict__ rin = &g_resid[ping][(size_t)b * RC * SEQLEN];
    float* __restrict__ rout = &g_resid[ping ^ 1][(size_t)b * RC * SEQLEN];
    float* __restrict__ sk = &g_skip[(size_t)b * RC * SEQLEN];

    // --- weights -> A form, pre-rounded to tf32
    const float2* fw2 = (const float2*)fw;
    const float2* gw2 = (const float2*)gw;
    for (int i = tid; i < 64 * 32; i += 256) {
        int row = i >> 5, ci = i & 31;
        int c = row & 31;
        float t0, t1, t2;
        if (row < 32) {
            float2 t = fw2[c * 32 + ci];
            t0 = t.x; t1 = t.y; t2 = rw[c * 32 + ci];
        } else {
            float2 t = gw2[c * 32 + ci];
            t0 = t.x; t1 = t.y; t2 = sw[c * 32 + ci];
        }
        wA[0 * 64 * WALD + row * WALD + ci] = wmma::__float_to_tf32(t0);
        wA[1 * 64 * WALD + row * WALD + ci] = wmma::__float_to_tf32(t1);
        wA[2 * 64 * WALD + row * WALD + ci] = wmma::__float_to_tf32(t2);
    }
    if (tid < 32) {
        bias[tid]      = fb[tid];
        bias[32 + tid] = gb[tid];
        bias[64 + tid] = rb[tid];
        bias[96 + tid] = sb[tid];
    }

    // --- residual halo load (zero-padded OOB); PAD and l0 multiples of 4
    {
        int c0 = (PAD + offA) & ~3;
        int c1 = (PAD + TL + offB + 4) & ~3;
        int w4 = (c1 - c0) >> 2;
        for (int i = tid; i < 32 * w4; i += 256) {
            int row = i / w4;
            int col = c0 + ((i - row * w4) << 2);
            int l = l0 - PAD + col;
            float4 v = make_float4(0.f, 0.f, 0.f, 0.f);
            if (l >= 0 && l < SEQLEN)
                v = *(const float4*)&rin[(size_t)row * SEQLEN + l];
            *(float4*)&halo[row * HS + col] = v;
        }
    }
    __syncthreads();

    int warp = tid >> 5;
    int lane = tid & 31;
    int n0 = warp * 16;
    int lcol = n0 + (lane & 15);
    int cbase = (lane >> 4) * 16;

    // ---------------- GEMM1: [f;g] = Wfg @ shifted residual ----------------
    wmma::fragment<wmma::accumulator, 16, 16, 8, float> acc[4];
#pragma unroll
    for (int mi = 0; mi < 4; mi++) wmma::fill_fragment(acc[mi], 0.f);

#pragma unroll
    for (int tap = 0; tap < 2; tap++) {
        const float* wAt = wA + tap * 64 * WALD;
        int tapOff = PAD + (tap ? offB : offA) + n0;
#pragma unroll
        for (int kf = 0; kf < 4; kf++) {
            wmma::fragment<wmma::matrix_a, 16, 16, 8, wmma::precision::tf32, wmma::row_major> a;
            wmma::fragment<wmma::matrix_b, 16, 16, 8, wmma::precision::tf32, wmma::row_major> bf;
            wmma::load_matrix_sync(bf, &halo[(kf * 8) * HS + tapOff], HS);
#pragma unroll
            for (int t = 0; t < bf.num_elements; t++)
                bf.x[t] = wmma::__float_to_tf32(bf.x[t]);
#pragma unroll
            for (int mi = 0; mi < 4; mi++) {
                wmma::load_matrix_sync(a, &wAt[(mi * 16) * WALD + kf * 8], WALD);
                wmma::mma_sync(acc[mi], a, bf, acc[mi]);
            }
        }
    }
#pragma unroll
    for (int mi = 0; mi < 4; mi++)
        wmma::store_matrix_sync(&fg[(mi * 16) * FGLD + n0], acc[mi], FGLD, wmma::mem_row_major);
    __syncwarp();

    // ---------------- lo = tf32((f+bf)*(g+bg))  (warp-local) ----------------
#pragma unroll
    for (int cc = 0; cc < 16; cc++) {
        int c = cbase + cc;
        float fv = fg[c * FGLD + lcol] + bias[c];
        float gv = fg[(32 + c) * FGLD + lcol] + bias[32 + c];
        lo[c * FGLD + lcol] = wmma::__float_to_tf32(fv * gv);
    }
    __syncwarp();

    // ---------------- GEMM2: [res;skip] = Wrs @ lo ----------------
#pragma unroll
    for (int mi = 0; mi < 4; mi++) wmma::fill_fragment(acc[mi], 0.f);
    {
        const float* wA2 = wA + 2 * 64 * WALD;
#pragma unroll
        for (int kf = 0; kf < 4; kf++) {
            wmma::fragment<wmma::matrix_a, 16, 16, 8, wmma::precision::tf32, wmma::row_major> a;
            wmma::fragment<wmma::matrix_b, 16, 16, 8, wmma::precision::tf32, wmma::row_major> bf;
            wmma::load_matrix_sync(bf, &lo[(kf * 8) * FGLD + n0], FGLD);
#pragma unroll
            for (int mi = 0; mi < 4; mi++) {
                wmma::load_matrix_sync(a, &wA2[(mi * 16) * WALD + kf * 8], WALD);
                wmma::mma_sync(acc[mi], a, bf, acc[mi]);
            }
        }
    }
#pragma unroll
    for (int mi = 0; mi < 4; mi++)
        wmma::store_matrix_sync(&fg[(mi * 16) * FGLD + n0], acc[mi], FGLD, wmma::mem_row_major);
    __syncwarp();

    // ---------------- residual + skip epilogue (fp32, warp-local) ----------------
#pragma unroll
    for (int cc = 0; cc < 16; cc++) {
        int c = cbase + cc;
        size_t gidx = (size_t)c * SEQLEN + l0 + lcol;
        float rv = halo[c * HS + PAD + lcol] + fg[c * FGLD + lcol] + bias[64 + c];
        float sv = fg[(32 + c) * FGLD + lcol] + bias[96 + c];
        if (!skipInit) sv += sk[gidx];
        rout[gidx] = rv;
        sk[gidx] = sv;
    }
}

// ----------------------------------------------------------------
// Kernel 3: fused head, zero conversion loops in mainloops.
//   hid = relu(W1e @ [relu(skip);1]);  out = W2e @ [hid;1]
// CTA = 128 positions, all 256 outputs; 8 warps, warp = 32 out rows.
// ----------------------------------------------------------------
__global__ __launch_bounds__(256, 1)
void k_head(float* __restrict__ out)
{
    extern __shared__ float smem[];
    float* hid = smem;                  // [264][HLDH], tf32-rounded
    float* bsk = smem + 264 * HLDH;     // [40][HLDH], tf32-rounded

    int tid = threadIdx.x;
    int b = blockIdx.y;
    int l0 = blockIdx.x * 128;

    // B tile: tf32(relu(skip)) rows 0-31, row 32 = 1, rows 33-39 = 0
    for (int i = tid; i < 32 * 32; i += 256) {
        int row = i >> 5, n4 = (i & 31) << 2;
        float4 v = *(const float4*)&g_skip[((size_t)b * RC + row) * SEQLEN + l0 + n4];
        v.x = wmma::__float_to_tf32(v.x > 0.f ? v.x : 0.f);
        v.y = wmma::__float_to_tf32(v.y > 0.f ? v.y : 0.f);
        v.z = wmma::__float_to_tf32(v.z > 0.f ? v.z : 0.f);
        v.w = wmma::__float_to_tf32(v.w > 0.f ? v.w : 0.f);
        *(float4*)&bsk[row * HLDH + n4] = v;
    }
    for (int i = tid; i < 8 * 128; i += 256) {
        int row = 32 + (i >> 7), col = i & 127;
        bsk[row * HLDH + col] = (row == 32) ? 1.f : 0.f;
    }
    // hid bias rows: row 256 = 1, rows 257-263 = 0
    for (int i = tid; i < 8 * 128; i += 256) {
        int row = 256 + (i >> 7), col = i & 127;
        hid[row * HLDH + col] = (row == 256) ? 1.f : 0.f;
    }
    __syncthreads();

    int warp = tid >> 5;
    wmma::fragment<wmma::accumulator, 16, 16, 8, float> acc[2][8];

    // ---------------- GEMM1 ----------------
#pragma unroll
    for (int mi = 0; mi < 2; mi++)
#pragma unroll
        for (int ni = 0; ni < 8; ni++) wmma::fill_fragment(acc[mi][ni], 0.f);

#pragma unroll
    for (int kf = 0; kf < 5; kf++) {
        wmma::fragment<wmma::matrix_b, 16, 16, 8, wmma::precision::tf32, wmma::row_major> bf[8];
#pragma unroll
        for (int ni = 0; ni < 8; ni++)
            wmma::load_matrix_sync(bf[ni], &bsk[(kf * 8) * HLDH + ni * 16], HLDH);
#pragma unroll
        for (int mi = 0; mi < 2; mi++) {
            wmma::fragment<wmma::matrix_a, 16, 16, 8, wmma::precision::tf32, wmma::row_major> a;
            wmma::load_matrix_sync(a, &g_w1e[(warp * 32 + mi * 16) * 40 + kf * 8], 40);
#pragma unroll
            for (int ni = 0; ni < 8; ni++)
                wmma::mma_sync(acc[mi][ni], a, bf[ni], acc[mi][ni]);
        }
    }
    // relu + tf32-round on fragments, store hid
#pragma unroll
    for (int mi = 0; mi < 2; mi++)
#pragma unroll
        for (int ni = 0; ni < 8; ni++) {
#pragma unroll
            for (int t = 0; t < acc[mi][ni].num_elements; t++) {
                float v = acc[mi][ni].x[t];
                acc[mi][ni].x[t] = wmma::__float_to_tf32(v > 0.f ? v : 0.f);
            }
            wmma::store_matrix_sync(&hid[(warp * 32 + mi * 16) * HLDH + ni * 16],
                                    acc[mi][ni], HLDH, wmma::mem_row_major);
        }
    __syncthreads();

    // ---------------- GEMM2: K = 264 ----------------
#pragma unroll
    for (int mi = 0; mi < 2; mi++)
#pragma unroll
        for (int ni = 0; ni < 8; ni++) wmma::fill_fragment(acc[mi][ni], 0.f);

    for (int kf = 0; kf < 33; kf++) {
        wmma::fragment<wmma::matrix_b, 16, 16, 8, wmma::precision::tf32, wmma::row_major> bf[8];
#pragma unroll
        for (int ni = 0; ni < 8; ni++)
            wmma::load_matrix_sync(bf[ni], &hid[(kf * 8) * HLDH + ni * 16], HLDH);
#pragma unroll
        for (int mi = 0; mi < 2; mi++) {
            wmma::fragment<wmma::matrix_a, 16, 16, 8, wmma::precision::tf32, wmma::row_major> a;
            wmma::load_matrix_sync(a, &g_w2e[(warp * 32 + mi * 16) * 264 + kf * 8], 264);
#pragma unroll
            for (int ni = 0; ni < 8; ni++)
                wmma::mma_sync(acc[mi][ni], a, bf[ni], acc[mi][ni]);
        }
    }
#pragma unroll
    for (int mi = 0; mi < 2; mi++)
#pragma unroll
        for (int ni = 0; ni < 8; ni++) {
            float* dst = &out[((size_t)b * OC + warp * 32 + mi * 16) * SEQLEN
                              + l0 + ni * 16];
            wmma::store_matrix_sync(dst, acc[mi][ni], SEQLEN, wmma::mem_row_major);
        }
}

// ----------------------------------------------------------------
extern "C" void kernel_launch(void* const* d_in, const int* in_sizes, int n_in,
                              void* d_out, int out_size)
{
    const float* x       = (const float*)d_in[0];
    const float* w_start = (const float*)d_in[1];
    const float* b_start = (const float*)d_in[2];
    const float* filt_w  = (const float*)d_in[3];
    const float* filt_b  = (const float*)d_in[4];
    const float* gate_w  = (const float*)d_in[5];
    const float* gate_b  = (const float*)d_in[6];
    const float* res_w   = (const float*)d_in[7];
    const float* res_b   = (const float*)d_in[8];
    const float* skip_w  = (const float*)d_in[9];
    const float* skip_b  = (const float*)d_in[10];
    const float* w_end1  = (const float*)d_in[11];
    const float* b_end1  = (const float*)d_in[12];
    const float* w_end2  = (const float*)d_in[13];
    const float* b_end2  = (const float*)d_in[14];
    float* out = (float*)d_out;

    static int smem_set = 0;
    if (!smem_set) {
        int hsMax = (TL + 2 * 256 + 11) & ~3;
        cudaFuncSetAttribute(k_layer_tc, cudaFuncAttributeMaxDynamicSharedMemorySize,
                             (SM_FIXED + 32 * hsMax) * (int)sizeof(float));
        cudaFuncSetAttribute(k_head, cudaFuncAttributeMaxDynamicSharedMemorySize,
                             (264 * HLDH + 40 * HLDH) * (int)sizeof(float));
        smem_set = 1;
    }

    {
        size_t n = (size_t)BATCH * RC * SEQLEN;
        k_start<<<(unsigned)((n + 255) / 256), 256>>>(x, w_start, b_start);
    }
    {
        int n = OC * 264 + OC * 40;
        k_prepw<<<(n + 255) / 256, 256>>>(w_end1, b_end1, w_end2, b_end2);
    }

    int ping = 0;
    dim3 gl(SEQLEN / TL, BATCH);
    for (int blk = 0; blk < NBLOCKS; blk++) {
        for (int i = 0; i < NLAYERS; i++) {
            int li = blk * NLAYERS + i;
            int offA, offB;
            if (i == 0) { offA = -1; offB = 0; }
            else { int h = 1 << (i - 1); offA = -h; offB = h; }
            int CO = -offA > offB ? -offA : offB;
            int PAD = (CO + 3) & ~3;
            int HS = (TL + 2 * PAD + 11) & ~3;
            int smemBytes = (SM_FIXED + 32 * HS) * (int)sizeof(float);
            k_layer_tc<<<gl, 256, smemBytes>>>(ping,
                filt_w + (size_t)li * RC * RC * 2, filt_b + (size_t)li * RC,
                gate_w + (size_t)li * RC * RC * 2, gate_b + (size_t)li * RC,
                res_w  + (size_t)li * RC * RC,     res_b  + (size_t)li * RC,
                skip_w + (size_t)li * RC * RC,     skip_b + (size_t)li * RC,
                offA, offB, PAD, HS, (li == 0) ? 1 : 0);
            ping ^= 1;
        }
    }

    dim3 gh(SEQLEN / 128, BATCH);
    k_head<<<gh, 256, (264 * HLDH + 40 * HLDH) * sizeof(float)>>>(out);
}